// round 5
// baseline (speedup 1.0000x reference)
#include <cuda_runtime.h>

// Problem constants: B=64, D=2048, UNITS=1024, NW=64
#define Dd     2048
#define UNITSn 1024
#define NWn    64

#define UPC    8                 // units per CTA
#define NCTA   (UNITSn / UPC)    // 128 CTAs
#define BKt    64                // k-tile width
#define NT     (Dd / BKt)        // 32 tiles
#define XST    68                // xs row stride (floats): conflict-free LDS.128
#define NTHR   512
#define STAGES 4                 // cp.async pipeline buffers (3 in flight)

__device__ __forceinline__ void fma2(unsigned long long& d,
                                     unsigned long long a,
                                     unsigned long long b) {
    asm("fma.rn.f32x2 %0, %1, %2, %0;" : "+l"(d) : "l"(a), "l"(b));
}
__device__ __forceinline__ void cp16(unsigned s, const void* g) {
    asm volatile("cp.async.cg.shared.global [%0], [%1], 16;" :: "r"(s), "l"(g));
}
__device__ __forceinline__ void cp_commit() {
    asm volatile("cp.async.commit_group;");
}
template <int N> __device__ __forceinline__ void cp_wait() {
    asm volatile("cp.async.wait_group %0;" :: "n"(N));
}
__device__ __forceinline__ unsigned mdiv(unsigned e, unsigned magic) {
    return (unsigned)(((unsigned long long)e * magic) >> 32);
}

// Prefetch x tile t (64 rows x 64 k fp32 = 16KB) into one xs stage.
__device__ __forceinline__ void load_x_tile(const float* __restrict__ x,
                                            unsigned xs_buf_u32, int t, int tid) {
    const int k0 = t * BKt;
    #pragma unroll
    for (int i = 0; i < 2; i++) {
        int idx = i * NTHR + tid;        // 0..1023 float4 slots
        int r   = idx >> 4;              // batch row 0..63
        int c   = (idx & 15) << 2;       // k offset 0,4,...,60
        cp16(xs_buf_u32 + (unsigned)((r * XST + c) * 4),
             x + (long)r * Dd + k0 + c);
    }
    cp_commit();
}

// ---------------------------------------------------------------------------
// Fused: build 8 W rows (8x2048 fp32) in smem from hashed indices, then GEMM
// vs x streamed through a 4-stage cp.async pipeline. 512 threads (4 warps per
// SMSP for latency hiding). Warp z in [0,16) owns k-segment of 4 per 64-tile;
// lane owns batch rows {lane, lane+32}; 8 units -> 16 f32x2 accumulators.
// W smem reads are warp-uniform broadcasts. Cross-z smem reduction + bias at
// the end; no atomics, no device scratch, one launch.
// ---------------------------------------------------------------------------
__global__ __launch_bounds__(NTHR, 1) void fused_kernel(const float* __restrict__ x,
                                                        const float* __restrict__ w,
                                                        const float* __restrict__ bias,
                                                        const int* __restrict__ indices,
                                                        float* __restrict__ out,
                                                        int L, unsigned magicL) {
    extern __shared__ float sm[];
    float* ws  = sm;                         // [UPC][Dd]          64 KB (reused as reduce buf)
    float* xs  = sm + UPC * Dd;              // [STAGES][64][XST]  69.6 KB
    float* wsm = xs + STAGES * 64 * XST;     // [NWn]

    const int tid = threadIdx.x;
    const int u0  = blockIdx.x * UPC;
    const unsigned xs_u32 = (unsigned)__cvta_generic_to_shared(xs);

    // Kick off x prefetch for tiles 0..2 (xs disjoint from ws; overlaps phase 1).
    #pragma unroll
    for (int s = 0; s < STAGES - 1; s++)
        load_x_tile(x, xs_u32 + s * 64 * XST * 4, s, tid);

    // ---- Phase 1: build W rows in smem (int4-vectorized, 8 loads in flight) ----
    if (tid < NWn) wsm[tid] = w[tid];
    const float4 z4 = make_float4(0.f, 0.f, 0.f, 0.f);
    #pragma unroll
    for (int i = 0; i < 8; i++) ((float4*)ws)[i * NTHR + tid] = z4;  // zero 64KB
    __syncthreads();

    {
        const int NWL4 = 16 * L;                       // int4 count per unit
        const int4* ind4 = (const int4*)indices + (long)u0 * NWL4;
        for (int e4 = tid; e4 < NWL4; e4 += NTHR) {
            int4 v[UPC];
            #pragma unroll
            for (int uu = 0; uu < UPC; uu++)
                v[uu] = __ldg(ind4 + (long)uu * NWL4 + e4);
            const int e = e4 * 4;
            const unsigned k0 = mdiv(e,     magicL);
            const unsigned k1 = mdiv(e + 1, magicL);
            const unsigned k2 = mdiv(e + 2, magicL);
            const unsigned k3 = mdiv(e + 3, magicL);
            #pragma unroll
            for (int uu = 0; uu < UPC; uu++) {
                float* wrow = ws + uu * Dd;
                unsigned p;
                p = (unsigned)(v[uu].x - 1); if (p < (unsigned)Dd) wrow[p] = wsm[k0];
                p = (unsigned)(v[uu].y - 1); if (p < (unsigned)Dd) wrow[p] = wsm[k1];
                p = (unsigned)(v[uu].z - 1); if (p < (unsigned)Dd) wrow[p] = wsm[k2];
                p = (unsigned)(v[uu].w - 1); if (p < (unsigned)Dd) wrow[p] = wsm[k3];
            }
        }
    }
    __syncthreads();   // ws ready for all warps

    // ---- Phase 2: pipelined GEMM ----
    const int lane = tid & 31;    // batch rows lane and lane+32
    const int z    = tid >> 5;    // warp id = k-segment of 4 within each tile

    unsigned long long acc[2][UPC];
    #pragma unroll
    for (int r = 0; r < 2; r++)
        #pragma unroll
        for (int j = 0; j < UPC; j++) acc[r][j] = 0ULL;   // (0.0f, 0.0f)

    for (int t = 0; t < NT; t++) {
        if (t < NT - 2) cp_wait<2>();
        else if (t == NT - 2) cp_wait<1>();
        else cp_wait<0>();
        __syncthreads();

        const float* xb0 = xs + (t & (STAGES - 1)) * 64 * XST + lane * XST + z * 4;
        const float* wb  = ws + t * BKt + z * 4;

        ulonglong2 xv0 = *(const ulonglong2*)(xb0);            // k..k+3, row lane
        ulonglong2 xv1 = *(const ulonglong2*)(xb0 + 32 * XST); // k..k+3, row lane+32
        #pragma unroll
        for (int j = 0; j < UPC; j++) {
            ulonglong2 wv = *(const ulonglong2*)(wb + j * Dd);  // warp-uniform
            fma2(acc[0][j], xv0.x, wv.x);
            fma2(acc[0][j], xv0.y, wv.y);
            fma2(acc[1][j], xv1.x, wv.x);
            fma2(acc[1][j], xv1.y, wv.y);
        }

        // Refill the stage consumed 1 iteration ago (all warps passed the sync).
        if (t + STAGES - 1 < NT)
            load_x_tile(x, xs_u32 + ((t + STAGES - 1) & (STAGES - 1)) * 64 * XST * 4,
                        t + STAGES - 1, tid);
    }
    __syncthreads();   // all ws reads done; safe to overlay reduce buffer

    // ---- Cross-z reduction (overlay ws) + bias + store ----
    float* red = ws;   // [16][64][UPC]
    #pragma unroll
    for (int r = 0; r < 2; r++) {
        const int b = lane + 32 * r;
        #pragma unroll
        for (int j = 0; j < UPC; j += 2) {
            unsigned long long v0 = acc[r][j], v1 = acc[r][j + 1];
            float s0 = __uint_as_float((unsigned)(v0 & 0xffffffffu)) +
                       __uint_as_float((unsigned)(v0 >> 32));
            float s1 = __uint_as_float((unsigned)(v1 & 0xffffffffu)) +
                       __uint_as_float((unsigned)(v1 >> 32));
            *(float2*)(red + (z * 64 + b) * UPC + j) = make_float2(s0, s1);
        }
    }
    __syncthreads();

    // 512 outputs per CTA, one per thread: b = tid>>3, j = tid&7.
    const int b2 = tid >> 3;
    const int jj = tid & 7;
    float s = 0.f;
    #pragma unroll
    for (int zz = 0; zz < 16; zz++)
        s += red[(zz * 64 + b2) * UPC + jj];
    s += __ldg(bias + u0 + jj);
    out[(long)b2 * UNITSn + u0 + jj] = s;
}

// ---------------------------------------------------------------------------
extern "C" void kernel_launch(void* const* d_in, const int* in_sizes, int n_in,
                              void* d_out, int out_size) {
    const float* x       = (const float*)d_in[0];
    const float* w       = (const float*)d_in[1];
    const float* bias    = (const float*)d_in[2];
    const int*   indices = (const int*)d_in[3];
    float*       out     = (float*)d_out;

    const int L = in_sizes[3] / (UNITSn * NWn);
    const unsigned magicL =
        (unsigned)((0x100000000ULL + (unsigned long long)L - 1) / (unsigned long long)L);

    const int smem_bytes =
        (UPC * Dd + STAGES * 64 * XST + NWn) * (int)sizeof(float);  // ~135 KB
    cudaFuncSetAttribute(fused_kernel, cudaFuncAttributeMaxDynamicSharedMemorySize,
                         smem_bytes);

    fused_kernel<<<NCTA, NTHR, smem_bytes>>>(x, w, bias, indices, out, L, magicL);
}